// round 11
// baseline (speedup 1.0000x reference)
#include <cuda_runtime.h>
#include <cstdint>

#define BB 32
#define SS 128
#define KN 12
#define KC 10
#define KT 22
#define DD 200
#define D4 50
#define CC 45
#define CP 48
#define FF 1000
#define NTOK 4096

#define FEATB (NTOK / 2)                   // 2048 (2 tokens/block)
#define TR_ELEMS (FF * CP)                 // 48000
#define TR_BLOCKS ((TR_ELEMS + 127) / 128) // 375

#define GT 64                              // tokens per gemm tile
#define NTILES (NTOK / GT)                 // 64
#define NPART 10                           // 5 w x 2 h partials
#define GEMMB (NTILES * NPART)             // 640
#define APITCH 108                         // shA pitch (floats)
#define BPITCH 104                         // shB pitch (floats): hi 0-47, lo 48-95
#define GEMM_SMEM (GT * APITCH * 4 + BPITCH * BPITCH * 4)  // 27648+43264=70912

__device__ float g_feat[NTOK * DD];        // [tok, 200] fp32
__device__ float g_Wthl[FF * 96];          // [k][96]: tf32 hi (0-47), lo (48-95)
__device__ float g_part[NPART * NTOK * CP]; // [p, tok, 48]
__device__ int   g_cnt[NTILES];            // zero-init; reset by reducer

__device__ __forceinline__ unsigned f2tf(float v) {
    unsigned r;
    asm("cvt.rna.tf32.f32 %0, %1;" : "=r"(r) : "f"(v));
    return r;
}

#define MMA8(d, a, B0, B1)                                                     \
    asm("mma.sync.aligned.m16n8k8.row.col.f32.tf32.tf32.f32 "                  \
        "{%0,%1,%2,%3}, {%4,%5,%6,%7}, {%8,%9}, {%0,%1,%2,%3};"                \
        : "+f"(d[0]), "+f"(d[1]), "+f"(d[2]), "+f"(d[3])                       \
        : "r"(a[0]), "r"(a[1]), "r"(a[2]), "r"(a[3]), "r"(B0), "r"(B1))

// ---------------------------------------------------------------------------
// Kernel 1 (R4-proven): masked gather+mean, 2 tokens/block; appended blocks
// build the tf32 hi/lo transposed weight table g_Wthl.
// ---------------------------------------------------------------------------
__global__ void __launch_bounds__(128, 16)
feat_tr_kernel(const int* __restrict__ ngram_ids,
               const int* __restrict__ ngram_mask,
               const int* __restrict__ ctx_ids,
               const int* __restrict__ ctx_mask,
               const float* __restrict__ embed,
               const float* __restrict__ W) {
    if (blockIdx.x >= FEATB) {
        int idx = (blockIdx.x - FEATB) * 128 + threadIdx.x;
        if (idx < TR_ELEMS) {
            int c = idx / FF;
            int k = idx - c * FF;
            float v = (c < CC) ? W[c * FF + k] : 0.0f;
            unsigned hi = f2tf(v);
            float rem = v - __uint_as_float(hi);
            unsigned lo = f2tf(rem);
            g_Wthl[k * 96 + c]      = __uint_as_float(hi);
            g_Wthl[k * 96 + 48 + c] = __uint_as_float(lo);
        }
        return;
    }

    const int half = threadIdx.x >> 6;
    const int lane = threadIdx.x & 63;
    const int tok  = blockIdx.x * 2 + half;

    __shared__ int s_act[2][24];
    __shared__ int s_cnt[2];

    if (lane < 32) {
        int m = 0, id = 0;
        if (lane < KN) {
            id = ngram_ids[tok * KN + lane];
            m  = ngram_mask[tok * KN + lane];
        } else if (lane < KT) {
            id = ctx_ids[tok * KC + lane - KN];
            m  = ctx_mask[tok * KC + lane - KN];
        }
        unsigned bal = __ballot_sync(0xffffffffu, m != 0);
        if (m) s_act[half][__popc(bal & ((1u << lane) - 1u))] = id;
        if (lane == 0) s_cnt[half] = __popc(bal);
    }
    __syncthreads();

    if (lane >= D4) return;

    const int n = s_cnt[half];
    const int* act = s_act[half];
    const float4* e4 = (const float4*)embed;

    float ax = 0.f, ay = 0.f, az = 0.f, aw = 0.f;
    int j = 0;
    for (; j + 4 <= n; j += 4) {
        float4 a = e4[(long long)act[j + 0] * D4 + lane];
        float4 b = e4[(long long)act[j + 1] * D4 + lane];
        float4 c = e4[(long long)act[j + 2] * D4 + lane];
        float4 d = e4[(long long)act[j + 3] * D4 + lane];
        ax += (a.x + b.x) + (c.x + d.x);
        ay += (a.y + b.y) + (c.y + d.y);
        az += (a.z + b.z) + (c.z + d.z);
        aw += (a.w + b.w) + (c.w + d.w);
    }
    for (; j < n; j++) {
        float4 a = e4[(long long)act[j] * D4 + lane];
        ax += a.x; ay += a.y; az += a.z; aw += a.w;
    }

    float inv = 1.0f / (float)(n > 0 ? n : 1);
    float4 r; r.x = ax * inv; r.y = ay * inv; r.z = az * inv; r.w = aw * inv;
    ((float4*)g_feat)[tok * D4 + lane] = r;
}

// ---------------------------------------------------------------------------
// Kernel 2: TF32x3 tensor-core GEMM. Grid 640 = 64 tiles x 5 w x 2 h.
// Block 64 thr = 2 warps; warp = 32 tokens (2 m16 A-frags) x 48 c (6 n8),
// k-chunk 104 (h=0) or 96 (h=1). Last-of-10 block reduces partials + bias.
// ---------------------------------------------------------------------------
__global__ void __launch_bounds__(64)
gemm_kernel(const float* __restrict__ bias,
            float* __restrict__ out) {
    extern __shared__ float dynsm[];
    float* shA = dynsm;                        // [64][APITCH]
    float* shB = dynsm + GT * APITCH;          // [BPITCH rows][BPITCH]
    __shared__ int s_last;

    const int q = blockIdx.x;
    const int tile = q / NPART;
    const int r10  = q - tile * NPART;
    const int w = r10 >> 1;
    const int h = r10 & 1;
    const int tokBase = tile * GT;
    const int b  = tokBase / SS;
    const int s0 = tokBase % SS;
    const int h0 = h * 104;
    const int klen4 = h ? 24 : 26;             // float4 cols staged
    const int nk8  = h ? 12 : 13;

    const int tid = threadIdx.x;
    const int lane = tid & 31;
    const int mb = (tid >> 5) * 32;            // warp token base in tile
    const int g = lane >> 2;                   // 0..7
    const int t = lane & 3;                    // 0..3

    // ---- stage A: 64 feat rows (w-shifted, zero halo), cols [h0, h0+klen)
    const float4* gf4 = (const float4*)g_feat;
    float4* shA4 = (float4*)shA;
    for (int i = tid; i < GT * (APITCH / 4); i += 64) {
        int r  = i / (APITCH / 4);
        int dv = i - r * (APITCH / 4);
        int s  = s0 + w - 2 + r;
        float4 v = make_float4(0.f, 0.f, 0.f, 0.f);
        if (s >= 0 && s < SS && dv < klen4)
            v = gf4[(b * SS + s) * D4 + h * 26 + dv];
        shA4[i] = v;
    }
    // ---- stage B: rows klen of g_Wthl (hi+lo, 96 floats -> pitch 104)
    const float4* wt4 = (const float4*)g_Wthl;
    float4* shB4 = (float4*)shB;
    {
        int klen = h ? 96 : 104;
        for (int i = tid; i < klen * 24; i += 64) {
            int r  = i / 24;
            int c4 = i - r * 24;
            shB4[r * (BPITCH / 4) + c4] = wt4[(w * DD + h0 + r) * 24 + c4];
        }
    }
    __syncthreads();

    // ---- mainloop
    float d[12][4];
    #pragma unroll
    for (int i = 0; i < 12; i++) { d[i][0]=0.f; d[i][1]=0.f; d[i][2]=0.f; d[i][3]=0.f; }

    for (int kk = 0; kk < nk8; kk++) {
        const int k0 = kk * 8;
        float af[8];
        af[0] = shA[(mb + g)      * APITCH + k0 + t];
        af[1] = shA[(mb + g + 8)  * APITCH + k0 + t];
        af[2] = shA[(mb + g)      * APITCH + k0 + t + 4];
        af[3] = shA[(mb + g + 8)  * APITCH + k0 + t + 4];
        af[4] = shA[(mb + 16 + g)     * APITCH + k0 + t];
        af[5] = shA[(mb + 16 + g + 8) * APITCH + k0 + t];
        af[6] = shA[(mb + 16 + g)     * APITCH + k0 + t + 4];
        af[7] = shA[(mb + 16 + g + 8) * APITCH + k0 + t + 4];

        unsigned ah[8], al[8];
        #pragma unroll
        for (int j = 0; j < 8; j++) {
            ah[j] = f2tf(af[j]);
            al[j] = f2tf(af[j] - __uint_as_float(ah[j]));
        }

        const float* b0p = &shB[(k0 + t) * BPITCH];
        const float* b1p = &shB[(k0 + t + 4) * BPITCH];
        #pragma unroll
        for (int n = 0; n < 6; n++) {
            unsigned bh0 = __float_as_uint(b0p[n * 8 + g]);
            unsigned bh1 = __float_as_uint(b1p[n * 8 + g]);
            unsigned bl0 = __float_as_uint(b0p[48 + n * 8 + g]);
            unsigned bl1 = __float_as_uint(b1p[48 + n * 8 + g]);
            MMA8(d[n],     (ah + 0), bh0, bh1);   // Ahi*Bhi  (frag0)
            MMA8(d[n],     (ah + 0), bl0, bl1);   // Ahi*Blo
            MMA8(d[n],     (al + 0), bh0, bh1);   // Alo*Bhi
            MMA8(d[6 + n], (ah + 4), bh0, bh1);   // frag1
            MMA8(d[6 + n], (ah + 4), bl0, bl1);
            MMA8(d[6 + n], (al + 4), bh0, bh1);
        }
    }

    // ---- write partials: D[row][col] layout per mma spec
    const int p = w * 2 + h;
    float2* part2 = (float2*)g_part;
    #pragma unroll
    for (int f = 0; f < 2; f++) {
        #pragma unroll
        for (int n = 0; n < 6; n++) {
            int row = tokBase + mb + f * 16 + g;
            int col = n * 8 + 2 * t;
            float2 v01; v01.x = d[f * 6 + n][0]; v01.y = d[f * 6 + n][1];
            float2 v23; v23.x = d[f * 6 + n][2]; v23.y = d[f * 6 + n][3];
            part2[(((long long)p * NTOK + row) * CP + col) >> 1] = v01;
            part2[(((long long)p * NTOK + row + 8) * CP + col) >> 1] = v23;
        }
    }

    // ---- last-of-10 reduction (fixed p-order -> deterministic)
    __threadfence();
    __syncthreads();
    if (tid == 0) {
        int old = atomicAdd(&g_cnt[tile], 1);
        s_last = (old == NPART - 1);
    }
    __syncthreads();
    if (!s_last) return;
    __threadfence();

    {
        const int tok = tokBase + tid;           // 64 threads, 1 token each
        const float4* p4 = (const float4*)g_part;
        float4 s[12];
        #pragma unroll
        for (int c4 = 0; c4 < 12; c4++) s[c4] = make_float4(0.f, 0.f, 0.f, 0.f);
        #pragma unroll
        for (int pp = 0; pp < NPART; pp++) {
            #pragma unroll
            for (int c4 = 0; c4 < 12; c4++) {
                float4 v = p4[((long long)pp * NTOK + tok) * 12 + c4];
                s[c4].x += v.x; s[c4].y += v.y; s[c4].z += v.z; s[c4].w += v.w;
            }
        }
        float* o = out + (long long)tok * CC;
        #pragma unroll
        for (int c4 = 0; c4 < 12; c4++) {
            int c0 = c4 * 4;
            if (c0 + 0 < CC) o[c0 + 0] = s[c4].x + bias[c0 + 0];
            if (c0 + 1 < CC) o[c0 + 1] = s[c4].y + bias[c0 + 1];
            if (c0 + 2 < CC) o[c0 + 2] = s[c4].z + bias[c0 + 2];
            if (c0 + 3 < CC) o[c0 + 3] = s[c4].w + bias[c0 + 3];
        }
    }
    __syncthreads();
    if (tid == 0) g_cnt[tile] = 0;               // reset for next graph replay
}

// ---------------------------------------------------------------------------
extern "C" void kernel_launch(void* const* d_in, const int* in_sizes, int n_in,
                              void* d_out, int out_size) {
    const int*   ngram_ids  = (const int*)d_in[0];
    const int*   ngram_mask = (const int*)d_in[1];
    const int*   ctx_ids    = (const int*)d_in[2];
    const int*   ctx_mask   = (const int*)d_in[3];
    const float* embed      = (const float*)d_in[4];
    const float* W          = (const float*)d_in[5];
    const float* bias       = (const float*)d_in[6];
    float* out = (float*)d_out;

    cudaFuncSetAttribute(gemm_kernel,
                         cudaFuncAttributeMaxDynamicSharedMemorySize, GEMM_SMEM);

    feat_tr_kernel<<<FEATB + TR_BLOCKS, 128>>>(
        ngram_ids, ngram_mask, ctx_ids, ctx_mask, embed, W);
    gemm_kernel<<<GEMMB, 64, GEMM_SMEM>>>(bias, out);
}

// round 12
// speedup vs baseline: 1.0506x; 1.0506x over previous
#include <cuda_runtime.h>
#include <cstdint>

#define BB 32
#define SS 128
#define KN 12
#define KC 10
#define KT 22
#define DD 200
#define D4 50
#define CC 45
#define CP 48
#define FF 1000
#define NTOK 4096

#define FEATB (NTOK / 2)                   // 2048 (2 tokens/block)
#define TR_ELEMS (FF * CP)                 // 48000
#define TR_BLOCKS ((TR_ELEMS + 127) / 128) // 375

#define GT 64                              // tokens per gemm tile
#define NTILES (NTOK / GT)                 // 64
#define NPART 10                           // 5 w x 2 h
#define GEMMB (NTILES * NPART)             // 640
#define AP2 106                            // shA pitch in float2 (53 float4)
#define BP2 50                             // shB pitch in float2 (25 float4)
#define GEMM_SMEM (GT * AP2 * 8 + 104 * BP2 * 8)   // 54272 + 41600 = 95872

__device__ float2 g_feathl[NTOK * DD];     // [tok][200] (tf32 hi, lo)
__device__ float2 g_Wthl[FF * CP];         // [k][48] (tf32 hi, lo)
__device__ float  g_part[NPART * NTOK * CP];
__device__ int    g_cnt[NTILES];           // zero-init; reset by reducer

__device__ __forceinline__ unsigned f2tf(float v) {
    unsigned r;
    asm("cvt.rna.tf32.f32 %0, %1;" : "=r"(r) : "f"(v));
    return r;
}

#define MMA8(d, a0, a1, a2, a3, B0, B1)                                        \
    asm("mma.sync.aligned.m16n8k8.row.col.f32.tf32.tf32.f32 "                  \
        "{%0,%1,%2,%3}, {%4,%5,%6,%7}, {%8,%9}, {%0,%1,%2,%3};"                \
        : "+f"(d[0]), "+f"(d[1]), "+f"(d[2]), "+f"(d[3])                       \
        : "r"(a0), "r"(a1), "r"(a2), "r"(a3), "r"(B0), "r"(B1))

// ---------------------------------------------------------------------------
// Kernel 1: masked gather+mean (R4-proven core), output as tf32 (hi,lo)
// pairs; appended blocks build the (hi,lo) transposed weight table.
// ---------------------------------------------------------------------------
__global__ void __launch_bounds__(128, 16)
feat_tr_kernel(const int* __restrict__ ngram_ids,
               const int* __restrict__ ngram_mask,
               const int* __restrict__ ctx_ids,
               const int* __restrict__ ctx_mask,
               const float* __restrict__ embed,
               const float* __restrict__ W) {
    if (blockIdx.x >= FEATB) {
        int idx = (blockIdx.x - FEATB) * 128 + threadIdx.x;
        if (idx < TR_ELEMS) {
            int c = idx / FF;
            int k = idx - c * FF;
            float v = (c < CC) ? W[c * FF + k] : 0.0f;
            unsigned hi = f2tf(v);
            float2 p;
            p.x = __uint_as_float(hi);
            p.y = __uint_as_float(f2tf(v - p.x));
            g_Wthl[k * CP + c] = p;
        }
        return;
    }

    const int half = threadIdx.x >> 6;
    const int lane = threadIdx.x & 63;
    const int tok  = blockIdx.x * 2 + half;

    __shared__ int s_act[2][24];
    __shared__ int s_cnt[2];

    if (lane < 32) {
        int m = 0, id = 0;
        if (lane < KN) {
            id = ngram_ids[tok * KN + lane];
            m  = ngram_mask[tok * KN + lane];
        } else if (lane < KT) {
            id = ctx_ids[tok * KC + lane - KN];
            m  = ctx_mask[tok * KC + lane - KN];
        }
        unsigned bal = __ballot_sync(0xffffffffu, m != 0);
        if (m) s_act[half][__popc(bal & ((1u << lane) - 1u))] = id;
        if (lane == 0) s_cnt[half] = __popc(bal);
    }
    __syncthreads();

    if (lane >= D4) return;

    const int n = s_cnt[half];
    const int* act = s_act[half];
    const float4* e4 = (const float4*)embed;

    float ax = 0.f, ay = 0.f, az = 0.f, aw = 0.f;
    int j = 0;
    for (; j + 4 <= n; j += 4) {
        float4 a = e4[(long long)act[j + 0] * D4 + lane];
        float4 b = e4[(long long)act[j + 1] * D4 + lane];
        float4 c = e4[(long long)act[j + 2] * D4 + lane];
        float4 d = e4[(long long)act[j + 3] * D4 + lane];
        ax += (a.x + b.x) + (c.x + d.x);
        ay += (a.y + b.y) + (c.y + d.y);
        az += (a.z + b.z) + (c.z + d.z);
        aw += (a.w + b.w) + (c.w + d.w);
    }
    for (; j < n; j++) {
        float4 a = e4[(long long)act[j] * D4 + lane];
        ax += a.x; ay += a.y; az += a.z; aw += a.w;
    }

    float inv = 1.0f / (float)(n > 0 ? n : 1);
    float v[4] = { ax * inv, ay * inv, az * inv, aw * inv };
    float2* o = &g_feathl[tok * DD + lane * 4];
    #pragma unroll
    for (int q = 0; q < 4; q++) {
        float2 p;
        p.x = __uint_as_float(f2tf(v[q]));
        p.y = __uint_as_float(f2tf(v[q] - p.x));
        o[q] = p;
    }
}

// ---------------------------------------------------------------------------
// Kernel 2: TF32x3 tensor GEMM, 256 thr (8 warps = 4 m-frags x 2 n-halves).
// Grid 640 = 64 tiles x 5 w x 2 h. smem 95.9 KB -> 2 CTA/SM, 16 warps/SM.
// No conversions in mainloop: A and B live as (hi,lo) float2 in smem.
// ---------------------------------------------------------------------------
__global__ void __launch_bounds__(256)
gemm_kernel(const float* __restrict__ bias,
            float* __restrict__ out) {
    extern __shared__ float2 dyn2[];
    float2* shA = dyn2;                      // [64][AP2]
    float2* shB = dyn2 + GT * AP2;           // [104][BP2]
    __shared__ int s_last;

    const int q = blockIdx.x;
    const int tile = q / NPART;
    const int r10  = q - tile * NPART;       // = w*2 + h
    const int w = r10 >> 1;
    const int h = r10 & 1;
    const int tokBase = tile * GT;
    const int b  = tokBase / SS;
    const int s0 = tokBase % SS;
    const int h0 = h * 104;                  // k offset
    const int klen = h ? 96 : 104;
    const int nk8  = h ? 12 : 13;

    const int tid = threadIdx.x;
    const int lane = tid & 31;
    const int wid = tid >> 5;
    const int mi = wid & 3;                  // m-frag (16 tokens)
    const int nh = wid >> 2;                 // n-half (24 cols)
    const int g = lane >> 2;                 // 0..7
    const int t = lane & 3;                  // 0..3

    // ---- stage A: 64 w-shifted feat rows, k cols [h0, h0+klen), as float4
    {
        const float4* src4 = (const float4*)g_feathl;
        float4* shA4 = (float4*)shA;
        const int kl4 = klen >> 1;           // float4 per row (52 or 48)
        for (int i = tid; i < GT * 52; i += 256) {
            int r  = i / 52;
            int c4 = i - r * 52;
            int s  = s0 + w - 2 + r;
            float4 v = make_float4(0.f, 0.f, 0.f, 0.f);
            if (s >= 0 && s < SS && c4 < kl4)
                v = src4[(b * SS + s) * 100 + (h0 >> 1) + c4];
            shA4[r * (AP2 / 2) + c4] = v;
        }
    }
    // ---- stage B: klen rows of g_Wthl, as float4 (24 per row)
    {
        const float4* wt4 = (const float4*)g_Wthl;
        float4* shB4 = (float4*)shB;
        for (int i = tid; i < 104 * 24; i += 256) {
            int r  = i / 24;
            int c4 = i - r * 24;
            float4 v = make_float4(0.f, 0.f, 0.f, 0.f);
            if (r < klen) v = wt4[(w * DD + h0 + r) * 24 + c4];
            shB4[r * (BP2 / 2) + c4] = v;
        }
    }
    __syncthreads();

    // ---- mainloop: per warp m16 x n24 x k(klen)
    float d0[4] = {0.f, 0.f, 0.f, 0.f};
    float d1[4] = {0.f, 0.f, 0.f, 0.f};
    float d2[4] = {0.f, 0.f, 0.f, 0.f};

    const int rowA = (mi * 16 + g) * AP2;
    for (int kk = 0; kk < nk8; kk++) {
        const int k0 = kk * 8;
        float2 a0 = shA[rowA + k0 + t];                  // (row g,   k t)
        float2 a1 = shA[rowA + 8 * AP2 + k0 + t];        // (row g+8, k t)
        float2 a2 = shA[rowA + k0 + t + 4];              // (row g,   k t+4)
        float2 a3 = shA[rowA + 8 * AP2 + k0 + t + 4];    // (row g+8, k t+4)
        unsigned ah0 = __float_as_uint(a0.x), al0 = __float_as_uint(a0.y);
        unsigned ah1 = __float_as_uint(a1.x), al1 = __float_as_uint(a1.y);
        unsigned ah2 = __float_as_uint(a2.x), al2 = __float_as_uint(a2.y);
        unsigned ah3 = __float_as_uint(a3.x), al3 = __float_as_uint(a3.y);

        const float2* br0 = &shB[(k0 + t) * BP2 + nh * 24];
        const float2* br1 = &shB[(k0 + t + 4) * BP2 + nh * 24];

        {
            float2 b0 = br0[g], b1 = br1[g];
            MMA8(d0, ah0, ah1, ah2, ah3, __float_as_uint(b0.x), __float_as_uint(b1.x));
            MMA8(d0, ah0, ah1, ah2, ah3, __float_as_uint(b0.y), __float_as_uint(b1.y));
            MMA8(d0, al0, al1, al2, al3, __float_as_uint(b0.x), __float_as_uint(b1.x));
        }
        {
            float2 b0 = br0[8 + g], b1 = br1[8 + g];
            MMA8(d1, ah0, ah1, ah2, ah3, __float_as_uint(b0.x), __float_as_uint(b1.x));
            MMA8(d1, ah0, ah1, ah2, ah3, __float_as_uint(b0.y), __float_as_uint(b1.y));
            MMA8(d1, al0, al1, al2, al3, __float_as_uint(b0.x), __float_as_uint(b1.x));
        }
        {
            float2 b0 = br0[16 + g], b1 = br1[16 + g];
            MMA8(d2, ah0, ah1, ah2, ah3, __float_as_uint(b0.x), __float_as_uint(b1.x));
            MMA8(d2, ah0, ah1, ah2, ah3, __float_as_uint(b0.y), __float_as_uint(b1.y));
            MMA8(d2, al0, al1, al2, al3, __float_as_uint(b0.x), __float_as_uint(b1.x));
        }
    }

    // ---- write partials (D frag layout: d[0]=(g,2t) d[1]=(g,2t+1) d[2],d[3]=row+8)
    {
        float2* part2 = (float2*)g_part;
        const int row = tokBase + mi * 16 + g;
        #pragma unroll
        for (int n = 0; n < 3; n++) {
            float* dn = (n == 0) ? d0 : (n == 1) ? d1 : d2;
            int col = nh * 24 + n * 8 + 2 * t;
            float2 v01; v01.x = dn[0]; v01.y = dn[1];
            float2 v23; v23.x = dn[2]; v23.y = dn[3];
            part2[(((long long)r10 * NTOK + row) * CP + col) >> 1] = v01;
            part2[(((long long)r10 * NTOK + row + 8) * CP + col) >> 1] = v23;
        }
    }

    // ---- last-of-10 reduction (fixed p-order -> deterministic)
    __threadfence();
    __syncthreads();
    if (tid == 0) {
        int old = atomicAdd(&g_cnt[tile], 1);
        s_last = (old == NPART - 1);
    }
    __syncthreads();
    if (!s_last) return;
    __threadfence();

    {
        const float4* p4 = (const float4*)g_part;
        for (int i = tid; i < GT * 12; i += 256) {
            int tokOff = i / 12;
            int c4 = i - tokOff * 12;
            int tok = tokBase + tokOff;
            float4 s = make_float4(0.f, 0.f, 0.f, 0.f);
            #pragma unroll
            for (int pp = 0; pp < NPART; pp++) {
                float4 v = p4[((long long)pp * NTOK + tok) * 12 + c4];
                s.x += v.x; s.y += v.y; s.z += v.z; s.w += v.w;
            }
            int c0 = c4 * 4;
            float* o = out + (long long)tok * CC;
            if (c0 + 0 < CC) o[c0 + 0] = s.x + bias[c0 + 0];
            if (c0 + 1 < CC) o[c0 + 1] = s.y + bias[c0 + 1];
            if (c0 + 2 < CC) o[c0 + 2] = s.z + bias[c0 + 2];
            if (c0 + 3 < CC) o[c0 + 3] = s.w + bias[c0 + 3];
        }
    }
    __syncthreads();
    if (tid == 0) g_cnt[tile] = 0;           // reset for next graph replay
}

// ---------------------------------------------------------------------------
extern "C" void kernel_launch(void* const* d_in, const int* in_sizes, int n_in,
                              void* d_out, int out_size) {
    const int*   ngram_ids  = (const int*)d_in[0];
    const int*   ngram_mask = (const int*)d_in[1];
    const int*   ctx_ids    = (const int*)d_in[2];
    const int*   ctx_mask   = (const int*)d_in[3];
    const float* embed      = (const float*)d_in[4];
    const float* W          = (const float*)d_in[5];
    const float* bias       = (const float*)d_in[6];
    float* out = (float*)d_out;

    cudaFuncSetAttribute(gemm_kernel,
                         cudaFuncAttributeMaxDynamicSharedMemorySize, GEMM_SMEM);

    feat_tr_kernel<<<FEATB + TR_BLOCKS, 128>>>(
        ngram_ids, ngram_mask, ctx_ids, ctx_mask, embed, W);
    gemm_kernel<<<GEMMB, 256, GEMM_SMEM>>>(bias, out);
}

// round 13
// speedup vs baseline: 1.3453x; 1.2806x over previous
#include <cuda_runtime.h>

#define BB 32
#define SS 128
#define KN 12
#define KC 10
#define KT 22
#define DD 200
#define D4 50
#define CC 45
#define CP 48
#define CP4 12
#define FF 1000
#define NTOK 4096

#define FEATB (NTOK / 2)                   // 2048 (2 tokens/block)
#define TR_ELEMS (FF * CP)                 // 48000
#define TR_BLOCKS ((TR_ELEMS + 127) / 128) // 375

#define GT 32                              // tokens per gemm tile
#define NTILES (NTOK / GT)                 // 128
#define GEMMB (NTILES * 5)                 // 640
#define APAD 51                            // shA pitch in float4 (204 floats)
#define BROWS 40                           // B rows staged per stage (5 stages)

__device__ float g_feat[NTOK * DD];        // [tok, D]
__device__ float g_Wt[FF * CP];            // [k, 48] transposed+padded
__device__ float g_part[5 * NTOK * CP];    // [w, tok, 48]
__device__ int   g_cnt[NTILES];            // zero-init; reset by reducer

// ---------------------------------------------------------------------------
// Kernel 1 (R4-proven, unchanged): masked gather+mean, 2 tokens/block,
// ballot-compacted ids, reg-capped; W transpose appended to the grid.
// ---------------------------------------------------------------------------
__global__ void __launch_bounds__(128, 16)
feat_tr_kernel(const int* __restrict__ ngram_ids,
               const int* __restrict__ ngram_mask,
               const int* __restrict__ ctx_ids,
               const int* __restrict__ ctx_mask,
               const float* __restrict__ embed,
               const float* __restrict__ W) {
    if (blockIdx.x >= FEATB) {
        int idx = (blockIdx.x - FEATB) * 128 + threadIdx.x;
        if (idx < TR_ELEMS) {
            int c = idx / FF;
            int k = idx - c * FF;
            g_Wt[k * CP + c] = (c < CC) ? W[c * FF + k] : 0.0f;
        }
        return;
    }

    const int half = threadIdx.x >> 6;
    const int lane = threadIdx.x & 63;
    const int tok  = blockIdx.x * 2 + half;

    __shared__ int s_act[2][24];
    __shared__ int s_cnt[2];

    if (lane < 32) {
        int m = 0, id = 0;
        if (lane < KN) {
            id = ngram_ids[tok * KN + lane];
            m  = ngram_mask[tok * KN + lane];
        } else if (lane < KT) {
            id = ctx_ids[tok * KC + lane - KN];
            m  = ctx_mask[tok * KC + lane - KN];
        }
        unsigned bal = __ballot_sync(0xffffffffu, m != 0);
        if (m) s_act[half][__popc(bal & ((1u << lane) - 1u))] = id;
        if (lane == 0) s_cnt[half] = __popc(bal);
    }
    __syncthreads();

    if (lane >= D4) return;

    const int n = s_cnt[half];
    const int* act = s_act[half];
    const float4* e4 = (const float4*)embed;

    float ax = 0.f, ay = 0.f, az = 0.f, aw = 0.f;
    int j = 0;
    for (; j + 4 <= n; j += 4) {
        float4 a = e4[(long long)act[j + 0] * D4 + lane];
        float4 b = e4[(long long)act[j + 1] * D4 + lane];
        float4 c = e4[(long long)act[j + 2] * D4 + lane];
        float4 d = e4[(long long)act[j + 3] * D4 + lane];
        ax += (a.x + b.x) + (c.x + d.x);
        ay += (a.y + b.y) + (c.y + d.y);
        az += (a.z + b.z) + (c.z + d.z);
        aw += (a.w + b.w) + (c.w + d.w);
    }
    for (; j < n; j++) {
        float4 a = e4[(long long)act[j] * D4 + lane];
        ax += a.x; ay += a.y; az += a.z; aw += a.w;
    }

    float inv = 1.0f / (float)(n > 0 ? n : 1);
    float4 r; r.x = ax * inv; r.y = ay * inv; r.z = az * inv; r.w = aw * inv;
    ((float4*)g_feat)[tok * D4 + lane] = r;
}

// ---------------------------------------------------------------------------
// Kernel 2: per-window partial GEMM (R9 layout), B staged in 5x40-row
// chunks so smem = 33.8 KB -> 6 CTAs/SM (36 warps/SM). 2 tok x 4 c per
// thread; fused last-block reduction. Grid 640 = 128 tiles x 5 w.
// ---------------------------------------------------------------------------
__global__ void __launch_bounds__(192, 6)
gemm_kernel(const float* __restrict__ bias,
            float* __restrict__ out) {
    __shared__ float4 shA[GT * APAD];        // 26112 B
    __shared__ float4 shB[BROWS * CP4];      // 7680 B
    __shared__ int s_last;

    const int q = blockIdx.x;
    const int tile = q / 5;
    const int w = q - tile * 5;
    const int tokBase = tile * GT;
    const int b  = tokBase / SS;
    const int s0 = tokBase % SS;

    const int tid = threadIdx.x;
    const int tg = tid & 15;                 // tokens tg and tg+16
    const int cg = tid >> 4;                 // 0..11

    // stage A rows s0+w-2 .. s0+w+29 (zero halo)
    const float4* gf4 = (const float4*)g_feat;
    for (int i = tid; i < GT * D4; i += 192) {
        int r  = i / D4;
        int dv = i - r * D4;
        int s  = s0 + w - 2 + r;
        float4 v = make_float4(0.f, 0.f, 0.f, 0.f);
        if (s >= 0 && s < SS) v = gf4[(b * SS + s) * D4 + dv];
        shA[r * APAD + dv] = v;
    }

    float p00 = 0.f, p01 = 0.f, p02 = 0.f, p03 = 0.f;   // token tg
    float p10 = 0.f, p11 = 0.f, p12 = 0.f, p13 = 0.f;   // token tg+16
    const float4* Wt4 = (const float4*)g_Wt;

    #pragma unroll
    for (int st = 0; st < 5; st++) {
        __syncthreads();
        // stage B rows [w*200 + st*40, +40): 480 float4, 2.5 per thread
        for (int i = tid; i < BROWS * CP4; i += 192)
            shB[i] = Wt4[(w * DD + st * BROWS) * CP4 + i];
        __syncthreads();

        const float4* aRow0 = &shA[tg * APAD + st * 10];
        const float4* aRow1 = &shA[(tg + 16) * APAD + st * 10];
        #pragma unroll
        for (int dq = 0; dq < 10; dq++) {
            float4 a0 = aRow0[dq];
            float4 a1 = aRow1[dq];
            float4 b0 = shB[(dq * 4 + 0) * CP4 + cg];
            float4 b1 = shB[(dq * 4 + 1) * CP4 + cg];
            float4 b2 = shB[(dq * 4 + 2) * CP4 + cg];
            float4 b3 = shB[(dq * 4 + 3) * CP4 + cg];
            p00 = fmaf(a0.x, b0.x, p00); p01 = fmaf(a0.x, b0.y, p01);
            p02 = fmaf(a0.x, b0.z, p02); p03 = fmaf(a0.x, b0.w, p03);
            p10 = fmaf(a1.x, b0.x, p10); p11 = fmaf(a1.x, b0.y, p11);
            p12 = fmaf(a1.x, b0.z, p12); p13 = fmaf(a1.x, b0.w, p13);
            p00 = fmaf(a0.y, b1.x, p00); p01 = fmaf(a0.y, b1.y, p01);
            p02 = fmaf(a0.y, b1.z, p02); p03 = fmaf(a0.y, b1.w, p03);
            p10 = fmaf(a1.y, b1.x, p10); p11 = fmaf(a1.y, b1.y, p11);
            p12 = fmaf(a1.y, b1.z, p12); p13 = fmaf(a1.y, b1.w, p13);
            p00 = fmaf(a0.z, b2.x, p00); p01 = fmaf(a0.z, b2.y, p01);
            p02 = fmaf(a0.z, b2.z, p02); p03 = fmaf(a0.z, b2.w, p03);
            p10 = fmaf(a1.z, b2.x, p10); p11 = fmaf(a1.z, b2.y, p11);
            p12 = fmaf(a1.z, b2.z, p12); p13 = fmaf(a1.z, b2.w, p13);
            p00 = fmaf(a0.w, b3.x, p00); p01 = fmaf(a0.w, b3.y, p01);
            p02 = fmaf(a0.w, b3.z, p02); p03 = fmaf(a0.w, b3.w, p03);
            p10 = fmaf(a1.w, b3.x, p10); p11 = fmaf(a1.w, b3.y, p11);
            p12 = fmaf(a1.w, b3.z, p12); p13 = fmaf(a1.w, b3.w, p13);
        }
    }

    // write partials
    float4* part4 = (float4*)g_part;
    float4 v0; v0.x = p00; v0.y = p01; v0.z = p02; v0.w = p03;
    float4 v1; v1.x = p10; v1.y = p11; v1.z = p12; v1.w = p13;
    part4[((long long)w * NTOK + tokBase + tg) * CP4 + cg] = v0;
    part4[((long long)w * NTOK + tokBase + tg + 16) * CP4 + cg] = v1;

    // last-block-of-tile reduction (fixed w-order sum -> deterministic)
    __threadfence();
    __syncthreads();
    if (tid == 0) {
        int old = atomicAdd(&g_cnt[tile], 1);
        s_last = (old == 4);
    }
    __syncthreads();
    if (!s_last) return;
    __threadfence();

    #pragma unroll
    for (int half = 0; half < 2; half++) {
        int t = tg + half * 16;
        int tok = tokBase + t;
        float4 s = make_float4(0.f, 0.f, 0.f, 0.f);
        #pragma unroll
        for (int w2 = 0; w2 < 5; w2++) {
            float4 p = part4[((long long)w2 * NTOK + tok) * CP4 + cg];
            s.x += p.x; s.y += p.y; s.z += p.z; s.w += p.w;
        }
        int c0 = cg * 4;
        float* o = out + (long long)tok * CC;
        o[c0] = s.x + bias[c0];
        if (c0 + 1 < CC) o[c0 + 1] = s.y + bias[c0 + 1];
        if (c0 + 2 < CC) o[c0 + 2] = s.z + bias[c0 + 2];
        if (c0 + 3 < CC) o[c0 + 3] = s.w + bias[c0 + 3];
    }
    if (tid == 0) g_cnt[tile] = 0;           // reset for next graph replay
}

// ---------------------------------------------------------------------------
extern "C" void kernel_launch(void* const* d_in, const int* in_sizes, int n_in,
                              void* d_out, int out_size) {
    const int*   ngram_ids  = (const int*)d_in[0];
    const int*   ngram_mask = (const int*)d_in[1];
    const int*   ctx_ids    = (const int*)d_in[2];
    const int*   ctx_mask   = (const int*)d_in[3];
    const float* embed      = (const float*)d_in[4];
    const float* W          = (const float*)d_in[5];
    const float* bias       = (const float*)d_in[6];
    float* out = (float*)d_out;

    feat_tr_kernel<<<FEATB + TR_BLOCKS, 128>>>(
        ngram_ids, ngram_mask, ctx_ids, ctx_mask, embed, W);
    gemm_kernel<<<GEMMB, 192>>>(bias, out);
}